// round 5
// baseline (speedup 1.0000x reference)
#include <cuda_runtime.h>
#include <cuda_bf16.h>
#include <math.h>

#define Bb 4
#define Nn 1024
#define Ee 256
#define Hh 8
#define Dd 32

// ---------------- scratch (device globals; referenced ONLY inside kernels) ----
__device__ float g_Wh[(size_t)Hh*Bb*Nn*Dd];        // [h][b][n][d]  4MB
__device__ float g_s1[Hh*Bb*Nn];
__device__ float g_s2[Hh*Bb*Nn];
__device__ float g_attn[(size_t)Hh*Bb*Nn*Nn];      // 134MB
__device__ float g_x1[Bb*Nn*Ee];                   // GAT residual output
__device__ float g_tA[Bb*Nn*Ee];
__device__ float g_tB[Bb*Nn*Ee];
__device__ float g_q[Bb*Nn*Ee];
__device__ float g_k[Bb*Nn*Ee];
__device__ float g_v[Bb*Nn*Ee];
__device__ float g_o[Bb*Nn*Ee];
__device__ float g_eout[(size_t)Bb*Nn*Nn];         // e_out staging
__device__ float g_xout[Bb*Nn*Ee];                 // x staging
__device__ float g_psum[64*Ee];
__device__ float g_psq [64*Ee];
__device__ float g_cmean[Bb*Ee];
__device__ float g_crstd[Bb*Ee];

// ---------------- helpers ----------------
__device__ __forceinline__ float blockReduceSum(float v, float* sm) {
    sm[threadIdx.x] = v; __syncthreads();
    #pragma unroll
    for (int s = 128; s > 0; s >>= 1) {
        if (threadIdx.x < s) sm[threadIdx.x] += sm[threadIdx.x + s];
        __syncthreads();
    }
    float r = sm[0]; __syncthreads();
    return r;
}
__device__ __forceinline__ float blockReduceMax(float v, float* sm) {
    sm[threadIdx.x] = v; __syncthreads();
    #pragma unroll
    for (int s = 128; s > 0; s >>= 1) {
        if (threadIdx.x < s) sm[threadIdx.x] = fmaxf(sm[threadIdx.x], sm[threadIdx.x + s]);
        __syncthreads();
    }
    float r = sm[0]; __syncthreads();
    return r;
}

// ---------------- K1: Wh = x @ Wg (per head), s1/s2 reductions ----------------
__global__ void k_wh(const float* __restrict__ x, const float* __restrict__ Wg,
                     const float* __restrict__ a1, const float* __restrict__ a2) {
    int bn = blockIdx.x;              // b*N + n
    int b = bn >> 10, n = bn & 1023;
    int h = threadIdx.x >> 5, d = threadIdx.x & 31;
    __shared__ float xs[256];
    xs[threadIdx.x] = x[bn * 256 + threadIdx.x];
    __syncthreads();
    float acc = 0.f;
    const float* wp = Wg + h * 8192 + d;   // Wg[h][f][d]
    #pragma unroll 8
    for (int f = 0; f < 256; f++) acc = fmaf(xs[f], wp[f * 32], acc);
    g_Wh[((size_t)(h * Bb + b) * Nn + n) * 32 + d] = acc;
    float v1 = acc * a1[h * 32 + d];
    float v2 = acc * a2[h * 32 + d];
    #pragma unroll
    for (int o = 16; o > 0; o >>= 1) {
        v1 += __shfl_down_sync(0xffffffffu, v1, o);
        v2 += __shfl_down_sync(0xffffffffu, v2, o);
    }
    if (d == 0) {
        g_s1[(h * Bb + b) * Nn + n] = v1;
        g_s2[(h * Bb + b) * Nn + n] = v2;
    }
}

// ---------------- K2: GAT attention rows (leaky + mask + softmax) ----------------
__global__ void k_gat_attn(const int* __restrict__ adj) {
    int n = blockIdx.x & 1023;
    int b = (blockIdx.x >> 10) & 3;
    int h = blockIdx.x >> 12;
    int t = threadIdx.x;
    __shared__ float sm[256];
    float s1v = g_s1[(h * Bb + b) * Nn + n];
    const float* s2p = g_s2 + (h * Bb + b) * Nn;
    const int* ap = adj + (size_t)(b * Nn + n) * Nn;
    float ev[4];
    float mx = -INFINITY;
    #pragma unroll
    for (int i = 0; i < 4; i++) {
        int m = t + i * 256;
        float e = s1v + s2p[m];
        e = e >= 0.f ? e : 0.1f * e;
        if (ap[m] <= 0) e = -9e15f;
        ev[i] = e;
        mx = fmaxf(mx, e);
    }
    mx = blockReduceMax(mx, sm);
    float s = 0.f;
    #pragma unroll
    for (int i = 0; i < 4; i++) { ev[i] = __expf(ev[i] - mx); s += ev[i]; }
    s = blockReduceSum(s, sm);
    float inv = 1.0f / s;
    float* op = g_attn + (size_t)((h * Bb + b) * Nn + n) * Nn;
    #pragma unroll
    for (int i = 0; i < 4; i++) op[t + i * 256] = ev[i] * inv;
}

// ---------------- K3: e_out = mean over heads ----------------
__global__ void k_eout(float* __restrict__ out) {
    size_t i = (size_t)blockIdx.x * 256 + threadIdx.x;   // < B*N*N
    const size_t BNN = (size_t)Bb * Nn * Nn;
    float* dst = out ? out : g_eout;
    float s = 0.f;
    #pragma unroll
    for (int h = 0; h < 8; h++) s += g_attn[(size_t)h * BNN + i];
    dst[i] = s * 0.125f;
}

// ---------------- K4: hp = attn @ Wh, leaky(0.01), residual add ----------------
__global__ void k_hp(const float* __restrict__ x) {
    __shared__ float Whs[256 * 32];   // 32KB chunk of Wh rows
    int tile = blockIdx.x & 127;
    int b = (blockIdx.x >> 7) & 3;
    int h = blockIdx.x >> 9;
    int t = threadIdx.x, w = t >> 5, lane = t & 31;
    int n = tile * 8 + w;
    const float* whp  = g_Wh  + (size_t)(h * Bb + b) * Nn * 32;
    const float* arow = g_attn + (size_t)((h * Bb + b) * Nn + n) * Nn;
    float acc = 0.f;
    for (int c = 0; c < 4; c++) {
        #pragma unroll
        for (int i = 0; i < 32; i++) Whs[t + i * 256] = whp[c * 8192 + t + i * 256];
        __syncthreads();
        const float* ar = arow + c * 256;
        #pragma unroll 4
        for (int m = 0; m < 256; m++) acc = fmaf(ar[m], Whs[m * 32 + lane], acc);
        __syncthreads();
    }
    acc = acc >= 0.f ? acc : 0.01f * acc;
    int idx = (b * Nn + n) * 256 + h * 32 + lane;
    g_x1[idx] = x[idx] + acc;
}

// ---------------- K5: row norm (_cnorm axis=2), ddof=1 ----------------
// sel=0: g_x1 -> g_tA ; sel=1: g_tA -> g_tB
__global__ void k_rownorm(int sel) {
    __shared__ float sm[256];
    const float* in = sel ? g_tA : g_x1;
    float* out      = sel ? g_tB : g_tA;
    int bn = blockIdx.x, t = threadIdx.x;
    float v = in[bn * 256 + t];
    float mean = blockReduceSum(v, sm) * (1.0f / 256.0f);
    float dd = v - mean;
    float var = blockReduceSum(dd * dd, sm) * (1.0f / 255.0f);
    out[bn * 256 + t] = dd / (sqrtf(var) + 1e-6f);
}

// ---------------- K6: column norm (_cnorm axis=1) split reduction ----------------
// sel=0: stats over g_tA ; sel=1: stats over g_tB
__global__ void k_colpart(int sel) {
    const float* in = sel ? g_tB : g_tA;
    int b = blockIdx.x >> 4, tl = blockIdx.x & 15;
    int e = threadIdx.x;
    float s = 0.f, sq = 0.f;
    const float* p = in + ((size_t)b * Nn + tl * 64) * 256 + e;
    #pragma unroll 4
    for (int i = 0; i < 64; i++) {
        float v = p[i * 256];
        s += v; sq += v * v;
    }
    g_psum[blockIdx.x * 256 + e] = s;
    g_psq [blockIdx.x * 256 + e] = sq;
}
__global__ void k_colstats() {
    int b = blockIdx.x, e = threadIdx.x;
    float s = 0.f, sq = 0.f;
    #pragma unroll
    for (int t = 0; t < 16; t++) {
        s  += g_psum[(b * 16 + t) * 256 + e];
        sq += g_psq [(b * 16 + t) * 256 + e];
    }
    float mean = s * (1.0f / 1024.0f);
    float var = (sq - 1024.0f * mean * mean) * (1.0f / 1023.0f);
    var = fmaxf(var, 0.f);
    g_cmean[b * 256 + e] = mean;
    g_crstd[b * 256 + e] = 1.0f / (sqrtf(var) + 1e-6f);
}
// sel=0: g_tA -> g_tB ; sel=1: g_tB -> g_tA
__global__ void k_colapply(int sel) {
    const float* in = sel ? g_tB : g_tA;
    float* out      = sel ? g_tA : g_tB;
    int i = blockIdx.x * 256 + threadIdx.x;   // < B*N*E
    int b = i >> 18;
    int e = i & 255;
    out[i] = (in[i] - g_cmean[b * 256 + e]) * g_crstd[b * 256 + e];
}

// ---------------- K7: GEMM  C[M,256] = A[M,256] @ W[256,256]^T + bias ----------
// asel: 0=g_tB, 1=g_tA, 2=g_o, 3=Aext (srcLayout applies)
// csel: 0=g_tA, 1=g_q, 2=g_k, 3=g_v, 4=Cext (fallback g_xout if null)
__global__ void k_gemm(const float* __restrict__ Aext, const float* __restrict__ W,
                       const float* __restrict__ bias, float* __restrict__ Cext,
                       int asel, int csel, int srcLayout) {
    __shared__ float As[64 * 65];
    __shared__ float Ws[64 * 65];
    const float* A = (asel == 0) ? g_tB : (asel == 1) ? g_tA : (asel == 2) ? g_o : Aext;
    float* C = (csel == 0) ? g_tA : (csel == 1) ? g_q : (csel == 2) ? g_k :
               (csel == 3) ? g_v : (Cext ? Cext : g_xout);
    int m0 = blockIdx.x * 64, i0 = blockIdx.y * 64;
    int t = threadIdx.x;
    int tr = t >> 4, ti = t & 15;
    float acc[4][4];
    #pragma unroll
    for (int a = 0; a < 4; a++)
        #pragma unroll
        for (int c = 0; c < 4; c++) acc[a][c] = 0.f;

    for (int kt = 0; kt < 256; kt += 64) {
        #pragma unroll
        for (int l = 0; l < 16; l++) {
            int idx = t + l * 256;
            int r = idx >> 6, k = idx & 63;
            int bn = m0 + r;
            int abase;
            if (srcLayout) { int b = bn >> 10, n = bn & 1023; abase = (n * Bb + b) * 256; }
            else abase = bn * 256;
            As[r * 65 + k] = A[abase + kt + k];
            Ws[r * 65 + k] = W[(i0 + r) * 256 + kt + k];
        }
        __syncthreads();
        #pragma unroll
        for (int k = 0; k < 64; k++) {
            float a[4], w[4];
            #pragma unroll
            for (int rr = 0; rr < 4; rr++) a[rr] = As[(tr * 4 + rr) * 65 + k];
            #pragma unroll
            for (int ii = 0; ii < 4; ii++) w[ii] = Ws[(ti * 4 + ii) * 65 + k];
            #pragma unroll
            for (int rr = 0; rr < 4; rr++)
                #pragma unroll
                for (int ii = 0; ii < 4; ii++)
                    acc[rr][ii] = fmaf(a[rr], w[ii], acc[rr][ii]);
        }
        __syncthreads();
    }
    #pragma unroll
    for (int rr = 0; rr < 4; rr++)
        #pragma unroll
        for (int ii = 0; ii < 4; ii++)
            C[(m0 + tr * 4 + rr) * 256 + i0 + ti * 4 + ii] = acc[rr][ii] + bias[i0 + ti * 4 + ii];
}

// ---------------- K8: MHA (scores, softmax, o = p @ v) — all symbol buffers ----
__global__ void k_mha() {
    __shared__ float ss[8 * 1024];    // 32KB
    __shared__ float Kt[64 * 33];     // 8.25KB
    __shared__ float qs[8 * 32];      // 1KB
    int tile = blockIdx.x & 127;
    int h = (blockIdx.x >> 7) & 7;
    int b = blockIdx.x >> 10;
    int t = threadIdx.x, w = t >> 5, lane = t & 31;
    int n0 = tile * 8;

    qs[t] = g_q[((size_t)b * Nn + n0 + w) * 256 + h * 32 + lane];
    __syncthreads();
    const float scale = 0.17677669529663689f;  // 1/sqrt(32)

    for (int m0 = 0; m0 < 1024; m0 += 64) {
        #pragma unroll
        for (int l = 0; l < 8; l++) {
            int idx = t + l * 256;
            int m = idx >> 5, d = idx & 31;
            Kt[m * 33 + d] = g_k[((size_t)b * Nn + m0 + m) * 256 + h * 32 + d];
        }
        __syncthreads();
        #pragma unroll
        for (int j = 0; j < 2; j++) {
            int m = j * 32 + lane;
            float s = 0.f;
            #pragma unroll
            for (int d = 0; d < 32; d++) s = fmaf(qs[w * 32 + d], Kt[m * 33 + d], s);
            ss[w * 1024 + m0 + m] = s * scale;
        }
        __syncthreads();
    }

    float mx = -INFINITY;
    #pragma unroll
    for (int j = 0; j < 32; j++) mx = fmaxf(mx, ss[w * 1024 + j * 32 + lane]);
    #pragma unroll
    for (int off = 16; off > 0; off >>= 1) mx = fmaxf(mx, __shfl_xor_sync(0xffffffffu, mx, off));
    float sum = 0.f;
    #pragma unroll
    for (int j = 0; j < 32; j++) {
        float p = __expf(ss[w * 1024 + j * 32 + lane] - mx);
        ss[w * 1024 + j * 32 + lane] = p;
        sum += p;
    }
    #pragma unroll
    for (int off = 16; off > 0; off >>= 1) sum += __shfl_xor_sync(0xffffffffu, sum, off);
    float inv = 1.0f / sum;
    __syncthreads();

    float acc = 0.f;
    for (int m0 = 0; m0 < 1024; m0 += 64) {
        #pragma unroll
        for (int l = 0; l < 8; l++) {
            int idx = t + l * 256;
            int m = idx >> 5, d = idx & 31;
            Kt[m * 33 + d] = g_v[((size_t)b * Nn + m0 + m) * 256 + h * 32 + d];
        }
        __syncthreads();
        #pragma unroll 4
        for (int m = 0; m < 64; m++)
            acc = fmaf(ss[w * 1024 + m0 + m], Kt[m * 33 + lane], acc);
        __syncthreads();
    }
    g_o[((size_t)b * Nn + n0 + w) * 256 + h * 32 + lane] = acc * inv;
}

// ---------------- launch ----------------
extern "C" void kernel_launch(void* const* d_in, const int* in_sizes, int n_in,
                              void* d_out, int out_size) {
    const float* x          = (const float*)d_in[0];   // (B,N,E)
    const float* src        = (const float*)d_in[1];   // (N,B,E)
    const int*   adj        = (const int*)  d_in[2];   // (B,N,N)
    const float* Wg         = (const float*)d_in[3];   // (H,E,D)
    const float* a1         = (const float*)d_in[4];   // (H,D)
    const float* a2         = (const float*)d_in[5];   // (H,D)
    const float* lin_w      = (const float*)d_in[6];   // (E,E)
    const float* lin_b      = (const float*)d_in[7];   // (E)
    const float* in_proj_w  = (const float*)d_in[8];   // (3E,E)
    const float* in_proj_b  = (const float*)d_in[9];   // (3E)
    const float* out_proj_w = (const float*)d_in[10];  // (E,E)
    const float* out_proj_b = (const float*)d_in[11];  // (E)
    float* out = (float*)d_out;

    const int XSZ = Bb * Nn * Ee;                // 1,048,576
    const int ESZ = Bb * Nn * Nn;                // 4,194,304

    float* x_dst;   // real device pointers only (d_out regions) or nullptr
    float* e_dst;
    if (out_size >= XSZ + ESZ) { x_dst = out;      e_dst = out + XSZ; }
    else if (out_size == ESZ)  { x_dst = nullptr;  e_dst = out; }
    else                       { x_dst = out;      e_dst = nullptr; }

    // GAT
    k_wh<<<Bb * Nn, 256>>>(x, Wg, a1, a2);
    k_gat_attn<<<Hh * Bb * Nn, 256>>>(adj);
    k_eout<<<(Bb * Nn * Nn) / 256, 256>>>(e_dst);
    k_hp<<<Hh * Bb * 128, 256>>>(x);

    // norm 1: g_x1 -> g_tA -> g_tB
    k_rownorm<<<Bb * Nn, 256>>>(0);
    k_colpart<<<Bb * 16, 256>>>(0);
    k_colstats<<<Bb, 256>>>();
    k_colapply<<<Bb * Nn, 256>>>(0);

    // lin: g_tB @ lin_w.T -> g_tA
    k_gemm<<<dim3(64, 4), 256>>>(nullptr, lin_w, lin_b, nullptr, 0, 0, 0);

    // norm 2: g_tA -> g_tB -> g_tA
    k_rownorm<<<Bb * Nn, 256>>>(1);
    k_colpart<<<Bb * 16, 256>>>(1);
    k_colstats<<<Bb, 256>>>();
    k_colapply<<<Bb * Nn, 256>>>(1);

    // q, k from g_tA; v from src
    k_gemm<<<dim3(64, 4), 256>>>(nullptr, in_proj_w,             in_proj_b,       nullptr, 1, 1, 0);
    k_gemm<<<dim3(64, 4), 256>>>(nullptr, in_proj_w + 256 * 256, in_proj_b + 256, nullptr, 1, 2, 0);
    k_gemm<<<dim3(64, 4), 256>>>(src,     in_proj_w + 512 * 256, in_proj_b + 512, nullptr, 3, 3, 1);

    // MHA (symbols) -> g_o
    k_mha<<<Bb * Hh * 128, 256>>>();

    // out projection: g_o @ out_proj_w.T -> x_dst (or g_xout staging)
    k_gemm<<<dim3(64, 4), 256>>>(nullptr, out_proj_w, out_proj_b, x_dst, 2, 4, 0);
}

// round 6
// speedup vs baseline: 1.3996x; 1.3996x over previous
#include <cuda_runtime.h>
#include <cuda_bf16.h>
#include <math.h>

#define Bb 4
#define Nn 1024
#define Ee 256
#define Hh 8
#define Dd 32

// ---------------- scratch (device globals; referenced ONLY inside kernels) ----
__device__ float g_Wh[(size_t)Hh*Bb*Nn*Dd];        // [h][b][n][d]  4MB
__device__ float g_s1[Hh*Bb*Nn];
__device__ float g_s2[Hh*Bb*Nn];
__device__ float g_attn[(size_t)Hh*Bb*Nn*Nn];      // 134MB (GAT attn, then MHA probs)
__device__ float g_x1[Bb*Nn*Ee];                   // GAT residual output
__device__ float g_tA[Bb*Nn*Ee];
__device__ float g_tB[Bb*Nn*Ee];
__device__ float g_q[Bb*Nn*Ee];
__device__ float g_k[Bb*Nn*Ee];
__device__ float g_v[Bb*Nn*Ee];
__device__ float g_o[Bb*Nn*Ee];
__device__ float g_eout[(size_t)Bb*Nn*Nn];         // e_out staging
__device__ float g_xout[Bb*Nn*Ee];                 // x staging
__device__ float g_psum[64*Ee];
__device__ float g_psq [64*Ee];
__device__ float g_cmean[Bb*Ee];
__device__ float g_crstd[Bb*Ee];

// ---------------- helpers ----------------
__device__ __forceinline__ float blockReduceSum(float v, float* sm) {
    sm[threadIdx.x] = v; __syncthreads();
    #pragma unroll
    for (int s = 128; s > 0; s >>= 1) {
        if (threadIdx.x < s) sm[threadIdx.x] += sm[threadIdx.x + s];
        __syncthreads();
    }
    float r = sm[0]; __syncthreads();
    return r;
}
__device__ __forceinline__ float blockReduceMax(float v, float* sm) {
    sm[threadIdx.x] = v; __syncthreads();
    #pragma unroll
    for (int s = 128; s > 0; s >>= 1) {
        if (threadIdx.x < s) sm[threadIdx.x] = fmaxf(sm[threadIdx.x], sm[threadIdx.x + s]);
        __syncthreads();
    }
    float r = sm[0]; __syncthreads();
    return r;
}

// ---------------- K1: Wh = x @ Wg (per head), s1/s2 reductions ----------------
__global__ void k_wh(const float* __restrict__ x, const float* __restrict__ Wg,
                     const float* __restrict__ a1, const float* __restrict__ a2) {
    int bn = blockIdx.x;              // b*N + n
    int b = bn >> 10, n = bn & 1023;
    int h = threadIdx.x >> 5, d = threadIdx.x & 31;
    __shared__ float xs[256];
    xs[threadIdx.x] = x[bn * 256 + threadIdx.x];
    __syncthreads();
    float acc = 0.f;
    const float* wp = Wg + h * 8192 + d;   // Wg[h][f][d]
    #pragma unroll 8
    for (int f = 0; f < 256; f++) acc = fmaf(xs[f], wp[f * 32], acc);
    g_Wh[((size_t)(h * Bb + b) * Nn + n) * 32 + d] = acc;
    float v1 = acc * a1[h * 32 + d];
    float v2 = acc * a2[h * 32 + d];
    #pragma unroll
    for (int o = 16; o > 0; o >>= 1) {
        v1 += __shfl_down_sync(0xffffffffu, v1, o);
        v2 += __shfl_down_sync(0xffffffffu, v2, o);
    }
    if (d == 0) {
        g_s1[(h * Bb + b) * Nn + n] = v1;
        g_s2[(h * Bb + b) * Nn + n] = v2;
    }
}

// ---------------- K2: GAT attention rows (leaky + mask + softmax) ----------------
__global__ void k_gat_attn(const int* __restrict__ adj) {
    int n = blockIdx.x & 1023;
    int b = (blockIdx.x >> 10) & 3;
    int h = blockIdx.x >> 12;
    int t = threadIdx.x;
    __shared__ float sm[256];
    float s1v = g_s1[(h * Bb + b) * Nn + n];
    const float* s2p = g_s2 + (h * Bb + b) * Nn;
    const int* ap = adj + (size_t)(b * Nn + n) * Nn;
    float ev[4];
    float mx = -INFINITY;
    #pragma unroll
    for (int i = 0; i < 4; i++) {
        int m = t + i * 256;
        float e = s1v + s2p[m];
        e = e >= 0.f ? e : 0.1f * e;
        if (ap[m] <= 0) e = -9e15f;
        ev[i] = e;
        mx = fmaxf(mx, e);
    }
    mx = blockReduceMax(mx, sm);
    float s = 0.f;
    #pragma unroll
    for (int i = 0; i < 4; i++) { ev[i] = __expf(ev[i] - mx); s += ev[i]; }
    s = blockReduceSum(s, sm);
    float inv = 1.0f / s;
    float* op = g_attn + (size_t)((h * Bb + b) * Nn + n) * Nn;
    #pragma unroll
    for (int i = 0; i < 4; i++) op[t + i * 256] = ev[i] * inv;
}

// ---------------- K3: e_out = mean over heads ----------------
__global__ void k_eout(float* __restrict__ out) {
    size_t i = (size_t)blockIdx.x * 256 + threadIdx.x;   // < B*N*N
    const size_t BNN = (size_t)Bb * Nn * Nn;
    float* dst = out ? out : g_eout;
    float s = 0.f;
    #pragma unroll
    for (int h = 0; h < 8; h++) s += g_attn[(size_t)h * BNN + i];
    dst[i] = s * 0.125f;
}

// ---------------- K4: AV GEMM: C[1024x32] = P[1024x1024] @ V[1024x32] ----------
// mode 0 (hp): B = g_Wh[h][b], epilogue leaky(0.01) + residual x -> g_x1
// mode 1 (pv): B = g_v slice h, epilogue plain -> g_o
// grid (8 tiles, 4 b, 8 h), 128 threads; thread tile 8 rows x 4 cols.
__global__ void k_av(const float* __restrict__ x, int mode) {
    __shared__ float As[32 * 132];   // [k][row] pad4, 16.5KB
    __shared__ float Ws[32 * 36];    // [m][d]  pad4, 4.5KB
    int tile = blockIdx.x, b = blockIdx.y, h = blockIdx.z;
    int t = threadIdx.x;
    int tr = t >> 3, tc = t & 7;
    int n0 = tile * 128;
    const float* ap  = g_attn + ((size_t)(h * Bb + b) * Nn + n0) * Nn;
    const float* whp = g_Wh + (size_t)(h * Bb + b) * Nn * 32;

    float acc[8][4];
    #pragma unroll
    for (int r = 0; r < 8; r++)
        #pragma unroll
        for (int c = 0; c < 4; c++) acc[r][c] = 0.f;

    for (int ch = 0; ch < 32; ch++) {
        int m0 = ch * 32;
        #pragma unroll
        for (int i = 0; i < 32; i++) {
            int idx = i * 128 + t;
            int row = idx >> 5, k = idx & 31;
            As[k * 132 + row] = ap[(size_t)row * Nn + m0 + k];
        }
        #pragma unroll
        for (int i = 0; i < 8; i++) {
            int idx = i * 128 + t;
            int m = idx >> 5, d = idx & 31;
            Ws[m * 36 + d] = (mode == 0)
                ? whp[(m0 + m) * 32 + d]
                : g_v[((size_t)b * Nn + m0 + m) * 256 + h * 32 + d];
        }
        __syncthreads();
        #pragma unroll
        for (int k = 0; k < 32; k++) {
            float a[8], w[4];
            *(float4*)&a[0] = *(const float4*)&As[k * 132 + tr * 8];
            *(float4*)&a[4] = *(const float4*)&As[k * 132 + tr * 8 + 4];
            *(float4*)&w[0] = *(const float4*)&Ws[k * 36 + tc * 4];
            #pragma unroll
            for (int r = 0; r < 8; r++)
                #pragma unroll
                for (int c = 0; c < 4; c++)
                    acc[r][c] = fmaf(a[r], w[c], acc[r][c]);
        }
        __syncthreads();
    }
    #pragma unroll
    for (int r = 0; r < 8; r++) {
        int n = n0 + tr * 8 + r;
        #pragma unroll
        for (int c = 0; c < 4; c++) {
            int idx = (b * Nn + n) * 256 + h * 32 + tc * 4 + c;
            float v = acc[r][c];
            if (mode == 0) {
                v = v >= 0.f ? v : 0.01f * v;
                g_x1[idx] = x[idx] + v;
            } else {
                g_o[idx] = v;
            }
        }
    }
}

// ---------------- K5: row norm (_cnorm axis=2), ddof=1 ----------------
// sel=0: g_x1 -> g_tA ; sel=1: g_tA -> g_tB
__global__ void k_rownorm(int sel) {
    __shared__ float sm[256];
    const float* in = sel ? g_tA : g_x1;
    float* out      = sel ? g_tB : g_tA;
    int bn = blockIdx.x, t = threadIdx.x;
    float v = in[bn * 256 + t];
    float mean = blockReduceSum(v, sm) * (1.0f / 256.0f);
    float dd = v - mean;
    float var = blockReduceSum(dd * dd, sm) * (1.0f / 255.0f);
    out[bn * 256 + t] = dd / (sqrtf(var) + 1e-6f);
}

// ---------------- K6: column norm (_cnorm axis=1) split reduction ----------------
__global__ void k_colpart(int sel) {
    const float* in = sel ? g_tB : g_tA;
    int b = blockIdx.x >> 4, tl = blockIdx.x & 15;
    int e = threadIdx.x;
    float s = 0.f, sq = 0.f;
    const float* p = in + ((size_t)b * Nn + tl * 64) * 256 + e;
    #pragma unroll 4
    for (int i = 0; i < 64; i++) {
        float v = p[i * 256];
        s += v; sq += v * v;
    }
    g_psum[blockIdx.x * 256 + e] = s;
    g_psq [blockIdx.x * 256 + e] = sq;
}
__global__ void k_colstats() {
    int b = blockIdx.x, e = threadIdx.x;
    float s = 0.f, sq = 0.f;
    #pragma unroll
    for (int t = 0; t < 16; t++) {
        s  += g_psum[(b * 16 + t) * 256 + e];
        sq += g_psq [(b * 16 + t) * 256 + e];
    }
    float mean = s * (1.0f / 1024.0f);
    float var = (sq - 1024.0f * mean * mean) * (1.0f / 1023.0f);
    var = fmaxf(var, 0.f);
    g_cmean[b * 256 + e] = mean;
    g_crstd[b * 256 + e] = 1.0f / (sqrtf(var) + 1e-6f);
}
__global__ void k_colapply(int sel) {
    const float* in = sel ? g_tB : g_tA;
    float* out      = sel ? g_tA : g_tB;
    int i = blockIdx.x * 256 + threadIdx.x;   // < B*N*E
    int b = i >> 18;
    int e = i & 255;
    out[i] = (in[i] - g_cmean[b * 256 + e]) * g_crstd[b * 256 + e];
}

// ---------------- K7: GEMM  C[M,256] = A[M,256] @ W[256,256]^T + bias ----------
// asel: 0=g_tB, 1=g_tA, 2=g_o, 3=Aext (srcLayout applies)
// csel: 0=g_tA, 1=g_q, 2=g_k, 3=g_v, 4=Cext (fallback g_xout if null)
__global__ void k_gemm(const float* __restrict__ Aext, const float* __restrict__ W,
                       const float* __restrict__ bias, float* __restrict__ Cext,
                       int asel, int csel, int srcLayout) {
    __shared__ float As[64 * 65];
    __shared__ float Ws[64 * 65];
    const float* A = (asel == 0) ? g_tB : (asel == 1) ? g_tA : (asel == 2) ? g_o : Aext;
    float* C = (csel == 0) ? g_tA : (csel == 1) ? g_q : (csel == 2) ? g_k :
               (csel == 3) ? g_v : (Cext ? Cext : g_xout);
    int m0 = blockIdx.x * 64, i0 = blockIdx.y * 64;
    int t = threadIdx.x;
    int tr = t >> 4, ti = t & 15;
    float acc[4][4];
    #pragma unroll
    for (int a = 0; a < 4; a++)
        #pragma unroll
        for (int c = 0; c < 4; c++) acc[a][c] = 0.f;

    for (int kt = 0; kt < 256; kt += 64) {
        #pragma unroll
        for (int l = 0; l < 16; l++) {
            int idx = t + l * 256;
            int r = idx >> 6, k = idx & 63;
            int bn = m0 + r;
            int abase;
            if (srcLayout) { int b = bn >> 10, n = bn & 1023; abase = (n * Bb + b) * 256; }
            else abase = bn * 256;
            As[r * 65 + k] = A[abase + kt + k];
            Ws[r * 65 + k] = W[(i0 + r) * 256 + kt + k];
        }
        __syncthreads();
        #pragma unroll
        for (int k = 0; k < 64; k++) {
            float a[4], w[4];
            #pragma unroll
            for (int rr = 0; rr < 4; rr++) a[rr] = As[(tr * 4 + rr) * 65 + k];
            #pragma unroll
            for (int ii = 0; ii < 4; ii++) w[ii] = Ws[(ti * 4 + ii) * 65 + k];
            #pragma unroll
            for (int rr = 0; rr < 4; rr++)
                #pragma unroll
                for (int ii = 0; ii < 4; ii++)
                    acc[rr][ii] = fmaf(a[rr], w[ii], acc[rr][ii]);
        }
        __syncthreads();
    }
    #pragma unroll
    for (int rr = 0; rr < 4; rr++)
        #pragma unroll
        for (int ii = 0; ii < 4; ii++)
            C[(m0 + tr * 4 + rr) * 256 + i0 + ti * 4 + ii] = acc[rr][ii] + bias[i0 + ti * 4 + ii];
}

// ---------------- K8: QK^T + fused softmax -> P (into g_attn) --------------------
// grid (64 panels of 16 q-rows, 4 b, 8 h), 256 threads.
// Thread owns one q-row (row = t>>4) and cols {kt*64 + (t&15)*4 .. +3}.
__global__ void k_qk() {
    __shared__ float Qs[16 * 33];    // [row][d]
    __shared__ float Ks[32 * 68];    // [d][col] pad 4
    int t = threadIdx.x;
    int b = blockIdx.y, h = blockIdx.z;
    int q0 = blockIdx.x * 16;
    int row = t >> 4, cg = t & 15;

    #pragma unroll
    for (int i = 0; i < 2; i++) {
        int idx = i * 256 + t;
        int r = idx >> 5, d = idx & 31;
        Qs[r * 33 + d] = g_q[((size_t)b * Nn + q0 + r) * 256 + h * 32 + d];
    }
    __syncthreads();

    float s[64];
    for (int kt = 0; kt < 16; kt++) {
        #pragma unroll
        for (int i = 0; i < 8; i++) {
            int idx = i * 256 + t;
            int col = idx >> 5, d = idx & 31;
            Ks[d * 68 + col] = g_k[((size_t)b * Nn + kt * 64 + col) * 256 + h * 32 + d];
        }
        __syncthreads();
        float s0 = 0.f, s1 = 0.f, s2 = 0.f, s3 = 0.f;
        #pragma unroll
        for (int d = 0; d < 32; d++) {
            float qd = Qs[row * 33 + d];
            float4 kv = *(const float4*)&Ks[d * 68 + cg * 4];
            s0 = fmaf(qd, kv.x, s0);
            s1 = fmaf(qd, kv.y, s1);
            s2 = fmaf(qd, kv.z, s2);
            s3 = fmaf(qd, kv.w, s3);
        }
        s[kt * 4 + 0] = s0; s[kt * 4 + 1] = s1;
        s[kt * 4 + 2] = s2; s[kt * 4 + 3] = s3;
        __syncthreads();
    }

    const float scale = 0.17677669529663689f;  // 1/sqrt(32)
    float mx = -INFINITY;
    #pragma unroll
    for (int i = 0; i < 64; i++) { s[i] *= scale; mx = fmaxf(mx, s[i]); }
    #pragma unroll
    for (int o = 8; o > 0; o >>= 1) mx = fmaxf(mx, __shfl_xor_sync(0xffffffffu, mx, o));
    float sum = 0.f;
    #pragma unroll
    for (int i = 0; i < 64; i++) { s[i] = __expf(s[i] - mx); sum += s[i]; }
    #pragma unroll
    for (int o = 8; o > 0; o >>= 1) sum += __shfl_xor_sync(0xffffffffu, sum, o);
    float inv = 1.0f / sum;

    float* prow = g_attn + ((size_t)(h * Bb + b) * Nn + q0 + row) * Nn;
    #pragma unroll
    for (int kt = 0; kt < 16; kt++) {
        float4 v = make_float4(s[kt * 4] * inv, s[kt * 4 + 1] * inv,
                               s[kt * 4 + 2] * inv, s[kt * 4 + 3] * inv);
        *(float4*)&prow[kt * 64 + cg * 4] = v;
    }
}

// ---------------- launch ----------------
extern "C" void kernel_launch(void* const* d_in, const int* in_sizes, int n_in,
                              void* d_out, int out_size) {
    const float* x          = (const float*)d_in[0];   // (B,N,E)
    const float* src        = (const float*)d_in[1];   // (N,B,E)
    const int*   adj        = (const int*)  d_in[2];   // (B,N,N)
    const float* Wg         = (const float*)d_in[3];   // (H,E,D)
    const float* a1         = (const float*)d_in[4];   // (H,D)
    const float* a2         = (const float*)d_in[5];   // (H,D)
    const float* lin_w      = (const float*)d_in[6];   // (E,E)
    const float* lin_b      = (const float*)d_in[7];   // (E)
    const float* in_proj_w  = (const float*)d_in[8];   // (3E,E)
    const float* in_proj_b  = (const float*)d_in[9];   // (3E)
    const float* out_proj_w = (const float*)d_in[10];  // (E,E)
    const float* out_proj_b = (const float*)d_in[11];  // (E)
    float* out = (float*)d_out;

    const int XSZ = Bb * Nn * Ee;                // 1,048,576
    const int ESZ = Bb * Nn * Nn;                // 4,194,304

    float* x_dst;
    float* e_dst;
    if (out_size >= XSZ + ESZ) { x_dst = out;      e_dst = out + XSZ; }
    else if (out_size == ESZ)  { x_dst = nullptr;  e_dst = out; }
    else                       { x_dst = out;      e_dst = nullptr; }

    // GAT
    k_wh<<<Bb * Nn, 256>>>(x, Wg, a1, a2);
    k_gat_attn<<<Hh * Bb * Nn, 256>>>(adj);
    k_eout<<<(Bb * Nn * Nn) / 256, 256>>>(e_dst);
    k_av<<<dim3(8, Bb, Hh), 128>>>(x, 0);        // hp + leaky + residual -> g_x1

    // norm 1: g_x1 -> g_tA -> g_tB
    k_rownorm<<<Bb * Nn, 256>>>(0);
    k_colpart<<<Bb * 16, 256>>>(0);
    k_colstats<<<Bb, 256>>>();
    k_colapply<<<Bb * Nn, 256>>>(0);

    // lin: g_tB @ lin_w.T -> g_tA
    k_gemm<<<dim3(64, 4), 256>>>(nullptr, lin_w, lin_b, nullptr, 0, 0, 0);

    // norm 2: g_tA -> g_tB -> g_tA
    k_rownorm<<<Bb * Nn, 256>>>(1);
    k_colpart<<<Bb * 16, 256>>>(1);
    k_colstats<<<Bb, 256>>>();
    k_colapply<<<Bb * Nn, 256>>>(1);

    // q, k from g_tA; v from src
    k_gemm<<<dim3(64, 4), 256>>>(nullptr, in_proj_w,             in_proj_b,       nullptr, 1, 1, 0);
    k_gemm<<<dim3(64, 4), 256>>>(nullptr, in_proj_w + 256 * 256, in_proj_b + 256, nullptr, 1, 2, 0);
    k_gemm<<<dim3(64, 4), 256>>>(src,     in_proj_w + 512 * 256, in_proj_b + 512, nullptr, 3, 3, 1);

    // MHA: scores+softmax -> g_attn (reuse), then PV -> g_o
    k_qk<<<dim3(64, Bb, Hh), 256>>>();
    k_av<<<dim3(8, Bb, Hh), 128>>>(nullptr, 1);

    // out projection: g_o @ out_proj_w.T -> x_dst (or g_xout staging)
    k_gemm<<<dim3(64, 4), 256>>>(nullptr, out_proj_w, out_proj_b, x_dst, 2, 4, 0);
}